// round 1
// baseline (speedup 1.0000x reference)
#include <cuda_runtime.h>

// Problem constants
#define S_LEN 32768
#define HDIM  1024
#define H3    3072        // attn_w row stride (3*H)
#define BM    128         // s-rows per CTA
#define BN    128         // i-cols per tile
#define BK    16          // k-chunk
#define NTHR  256
#define GRID2 (S_LEN / BM)   // 256 CTAs for the main kernel

// Scratch (no allocations allowed -> __device__ globals)
__device__ float g_c[HDIM];       // c[i] = hidden . attn_w[i,0:2H] + b[i]
__device__ float g_part[GRID2];   // per-CTA partial sums of exp(logit)
__device__ float g_inv;           // 1 / total sum

// ---------------------------------------------------------------------------
// Kernel 1: c[i] = sum_{j<2H} hidden[j]*attn_w[i*3H+j] + attn_b[i]
// One warp per i. 1024 warps = 128 blocks * 8 warps.
// ---------------------------------------------------------------------------
__global__ void precompute_c_kernel(const float* __restrict__ hidden,
                                    const float* __restrict__ attn_w,
                                    const float* __restrict__ attn_b) {
    int warp = (blockIdx.x * blockDim.x + threadIdx.x) >> 5;
    int lane = threadIdx.x & 31;
    if (warp >= HDIM) return;
    const float* wrow = attn_w + (size_t)warp * H3;
    float s = 0.f;
    #pragma unroll 8
    for (int j = lane; j < 2 * HDIM; j += 32)
        s += hidden[j] * wrow[j];
    #pragma unroll
    for (int off = 16; off; off >>= 1)
        s += __shfl_down_sync(0xffffffffu, s, off);
    if (lane == 0) g_c[warp] = s + attn_b[warp];
}

// ---------------------------------------------------------------------------
// Kernel 2: fused  logit[s] = sum_i v[i]*tanh(c[i] + enc[s,:].W2[i,:])
//           out[s] = exp(logit[s]);  g_part[blk] = sum of exps in this block.
// 128x128 output tile per i-chunk, 16x16 thread grid, 8x8 values per thread.
// Inner product uses packed fma.rn.f32x2 (2 s-rows per instruction).
// ---------------------------------------------------------------------------
__global__ __launch_bounds__(NTHR, 2)
void attn_main_kernel(const float* __restrict__ enc,
                      const float* __restrict__ attn_w,
                      const float* __restrict__ v_w,
                      float* __restrict__ out) {
    __shared__ float As[BK][BM];     // As[k][s]  (k-major for broadcast reads)
    __shared__ float Bs[BK][BN];     // Bs[k][i]
    __shared__ float esum[16];

    const int tid = threadIdx.x;
    const int tx  = tid & 15;        // i-group: cols tx*8 .. tx*8+7
    const int ty  = tid >> 4;        // s-group: rows ty*8 .. ty*8+7
    const int s0  = blockIdx.x * BM;

    float part[8];
    #pragma unroll
    for (int r = 0; r < 8; r++) part[r] = 0.f;

    for (int it = 0; it < HDIM / BN; it++) {
        // acc[p][c]: packed pair of s-rows (2p, 2p+1) x i-col c
        unsigned long long acc[4][8];
        #pragma unroll
        for (int p = 0; p < 4; p++)
            #pragma unroll
            for (int c = 0; c < 8; c++) acc[p][c] = 0ull;

        for (int kt = 0; kt < HDIM; kt += BK) {
            // cooperative tile load: 128 rows x 16 k, as float4 (512 per tile)
            #pragma unroll
            for (int l = 0; l < 2; l++) {
                int idx = tid + l * NTHR;        // 0..511
                int row = idx >> 2;              // 0..127
                int kq  = idx & 3;               // float4 slot in k
                float4 va = *(const float4*)(enc + (size_t)(s0 + row) * HDIM + kt + kq * 4);
                As[kq * 4 + 0][row] = va.x;
                As[kq * 4 + 1][row] = va.y;
                As[kq * 4 + 2][row] = va.z;
                As[kq * 4 + 3][row] = va.w;
                float4 vb = *(const float4*)(attn_w + (size_t)(it * BN + row) * H3
                                             + 2 * HDIM + kt + kq * 4);
                Bs[kq * 4 + 0][row] = vb.x;
                Bs[kq * 4 + 1][row] = vb.y;
                Bs[kq * 4 + 2][row] = vb.z;
                Bs[kq * 4 + 3][row] = vb.w;
            }
            __syncthreads();

            #pragma unroll
            for (int k = 0; k < BK; k++) {
                // a: 4 packed pairs of consecutive s-rows (8-byte aligned)
                unsigned long long a2[4];
                const unsigned long long* arow =
                    reinterpret_cast<const unsigned long long*>(&As[k][ty * 8]);
                #pragma unroll
                for (int p = 0; p < 4; p++) a2[p] = arow[p];

                // b: 8 scalars via two vector loads, then splat-pack
                float4 blo = *(const float4*)&Bs[k][tx * 8];
                float4 bhi = *(const float4*)&Bs[k][tx * 8 + 4];
                float bv[8] = {blo.x, blo.y, blo.z, blo.w,
                               bhi.x, bhi.y, bhi.z, bhi.w};
                #pragma unroll
                for (int c = 0; c < 8; c++) {
                    unsigned long long b2;
                    unsigned int bu = __float_as_uint(bv[c]);
                    asm("mov.b64 %0, {%1, %1};" : "=l"(b2) : "r"(bu));
                    #pragma unroll
                    for (int p = 0; p < 4; p++) {
                        asm("fma.rn.f32x2 %0, %1, %2, %0;"
                            : "+l"(acc[p][c]) : "l"(a2[p]), "l"(b2));
                    }
                }
            }
            __syncthreads();
        }

        // epilogue for this i-tile: tanh + v-dot accumulation
        #pragma unroll
        for (int c = 0; c < 8; c++) {
            int i = it * BN + tx * 8 + c;
            float ci = g_c[i];
            float vi = __ldg(v_w + i);
            #pragma unroll
            for (int p = 0; p < 4; p++) {
                float2 e2 = *reinterpret_cast<float2*>(&acc[p][c]);
                part[2 * p + 0] += vi * tanhf(e2.x + ci);
                part[2 * p + 1] += vi * tanhf(e2.y + ci);
            }
        }
    }

    // reduce over the 16 tx threads sharing each s-row (segments of 16 lanes)
    #pragma unroll
    for (int r = 0; r < 8; r++) {
        float v = part[r];
        v += __shfl_down_sync(0xffffffffu, v, 8, 16);
        v += __shfl_down_sync(0xffffffffu, v, 4, 16);
        v += __shfl_down_sync(0xffffffffu, v, 2, 16);
        v += __shfl_down_sync(0xffffffffu, v, 1, 16);
        part[r] = v;
    }
    if (tx == 0) {
        float lsum = 0.f;
        #pragma unroll
        for (int r = 0; r < 8; r++) {
            // |logit| <= sum|v_i| ~ 25  ->  exp is safe without max-shift
            float ex = expf(part[r]);
            out[s0 + ty * 8 + r] = ex;
            lsum += ex;
        }
        esum[ty] = lsum;
    }
    __syncthreads();
    if (tid == 0) {
        float t = 0.f;
        #pragma unroll
        for (int y = 0; y < 16; y++) t += esum[y];
        g_part[blockIdx.x] = t;
    }
}

// ---------------------------------------------------------------------------
// Kernel 3: deterministic reduction of 256 block partials -> g_inv
// ---------------------------------------------------------------------------
__global__ void reduce_total_kernel() {
    __shared__ float sm[GRID2];
    int t = threadIdx.x;
    sm[t] = g_part[t];
    __syncthreads();
    #pragma unroll
    for (int o = GRID2 / 2; o > 0; o >>= 1) {
        if (t < o) sm[t] += sm[t + o];
        __syncthreads();
    }
    if (t == 0) g_inv = 1.f / sm[0];
}

// ---------------------------------------------------------------------------
// Kernel 4: normalize in place
// ---------------------------------------------------------------------------
__global__ void normalize_kernel(float* __restrict__ out) {
    int i = blockIdx.x * blockDim.x + threadIdx.x;
    if (i < S_LEN) out[i] *= g_inv;
}

// ---------------------------------------------------------------------------
// Inputs (metadata order): hidden[2048], encoder_output[S*H],
//                          attn_w[H*3H], attn_b[H], v_w[H]
// Output: float[S]
// ---------------------------------------------------------------------------
extern "C" void kernel_launch(void* const* d_in, const int* in_sizes, int n_in,
                              void* d_out, int out_size) {
    const float* hidden = (const float*)d_in[0];
    const float* enc    = (const float*)d_in[1];
    const float* attn_w = (const float*)d_in[2];
    const float* attn_b = (const float*)d_in[3];
    const float* v_w    = (const float*)d_in[4];
    float* out = (float*)d_out;

    precompute_c_kernel<<<128, 256>>>(hidden, attn_w, attn_b);
    attn_main_kernel<<<GRID2, NTHR>>>(enc, attn_w, v_w, out);
    reduce_total_kernel<<<1, GRID2>>>();
    normalize_kernel<<<S_LEN / 256, 256>>>(out);
}